// round 14
// baseline (speedup 1.0000x reference)
#include <cuda_runtime.h>
#include <cstdint>

// Problem constants
#define B_   8
#define F_   32
#define NN   256
#define MM   64
#define CO   64
#define CC   224
#define XDP  512     // dup'd X-tile row pitch in floats (each value stored twice)

typedef unsigned long long u64;

__device__ __forceinline__ float2 unpk2(u64 v) {
    float2 f; asm("mov.b64 {%0, %1}, %2;" : "=f"(f.x), "=f"(f.y) : "l"(v)); return f;
}
__device__ __forceinline__ u64 ffma2(u64 a, u64 b, u64 c) {
    u64 d; asm("fma.rn.f32x2 %0, %1, %2, %3;" : "=l"(d) : "l"(a), "l"(b), "l"(c)); return d;
}

// ---- cp.async ----
__device__ __forceinline__ void cp_async16(void* smem_dst, const void* gmem_src) {
    uint32_t s = (uint32_t)__cvta_generic_to_shared(smem_dst);
    asm volatile("cp.async.cg.shared.global [%0], [%1], 16;\n" :: "r"(s), "l"(gmem_src));
}
__device__ __forceinline__ void cp_commit() { asm volatile("cp.async.commit_group;\n"); }
template <int N>
__device__ __forceinline__ void cp_wait() { asm volatile("cp.async.wait_group %0;\n" :: "n"(N)); }

__device__ __forceinline__ void issue_panel_copy(float* dst, const float* src, int t) {
    const float4* s4 = (const float4*)src;
    float4* d4 = (float4*)dst;
#pragma unroll
    for (int i = 0; i < 4; ++i)          // 2048 float4 / 512 threads
        cp_async16(&d4[t + 512 * i], &s4[t + 512 * i]);
    cp_commit();
}

// X1[f][v] = sum_n X[f][n] * A[n][v].
// X tiles are stored DUPLICATED: Xdup[f][2n] == Xdup[f][2n+1] == X[f][n],
// so the FFMA2 "broadcast" operand is a direct 16B LDS (2 dup-pairs), no packs.
// Thread (ty4 = t>>6, tx4 = t&63): rows {ty4+8r, r<4}, cols {4*tx4 .. 4*tx4+3}.
// A loads: 1 x LDS.128 per k, reused by 4 rows (same as the 596us kernel).
__device__ __forceinline__ void nconv_step(
    const float* __restrict__ Ag,     // global A[b][m]: [256][256] fp32
    const float* Xsrc, float* Xdst,   // dup'd smem tiles [32][XDP] (may alias)
    float* As0, float* As1, float* As2,
    int t, int tx4, int ty4)
{
    u64 acc[4][2];
#pragma unroll
    for (int r = 0; r < 4; ++r) { acc[r][0] = 0ull; acc[r][1] = 0ull; }

    float* bufs[3] = { As0, As1, As2 };
    issue_panel_copy(As0, Ag, t);
    issue_panel_copy(As1, Ag + 8192, t);

#pragma unroll 1
    for (int kp = 0; kp < 8; ++kp) {
        if (kp < 7) cp_wait<1>(); else cp_wait<0>();
        __syncthreads();                       // panel kp visible to all
        if (kp + 2 < 8)
            issue_panel_copy(bufs[(kp + 2) % 3], Ag + (kp + 2) * 8192, t);
        // 3 buffers: buf (kp+2)%3 was last read at iter kp-1, which completed
        // before the barrier above -> no tail barrier needed.

        const float* As = bufs[kp % 3];

#pragma unroll 4
        for (int kq = 0; kq < 16; ++kq) {      // 2 k per iteration
            // dup-pair X loads: 16B broadcast per row = (dup(k0), dup(k1))
            ulonglong2 xp[4];
#pragma unroll
            for (int r = 0; r < 4; ++r)
                xp[r] = *(const ulonglong2*)&Xsrc[(ty4 + 8 * r) * XDP + kp * 64 + kq * 4];
#pragma unroll
            for (int j2 = 0; j2 < 2; ++j2) {
                int k = kq * 2 + j2;
                ulonglong2 a2 = *(const ulonglong2*)&As[k * NN + tx4 * 4];
#pragma unroll
                for (int r = 0; r < 4; ++r) {
                    u64 xd = j2 ? xp[r].y : xp[r].x;
                    acc[r][0] = ffma2(xd, a2.x, acc[r][0]);
                    acc[r][1] = ffma2(xd, a2.y, acc[r][1]);
                }
            }
        }
    }

    __syncthreads();   // all reads of Xsrc done -> in-place overwrite safe
#pragma unroll
    for (int r = 0; r < 4; ++r) {
        int row = ty4 + 8 * r;
        float2 p0 = unpk2(acc[r][0]);
        float2 p1 = unpk2(acc[r][1]);
        float4* d = (float4*)&Xdst[row * XDP + 8 * tx4];
        d[0] = make_float4(p0.x, p0.x, p0.y, p0.y);   // dup'd store
        d[1] = make_float4(p1.x, p1.x, p1.y, p1.y);
    }
    __syncthreads();   // Xdst visible
}

// Y[o][v] += sum_c W[o][cb+c] * h[c][v] over c in [0,32).  Scalar FFMA (12.7%
// of MACs).  h comes from a dup'd tile: two 16B loads give v0,v0,v1,v1 / v2,...
__device__ __forceinline__ void mix_step(
    const float* Bs,                  // dup'd smem tile [32][XDP]
    const float* __restrict__ W,      // [64][224] global (L1-resident)
    int cb,
    float (&yacc)[8][4],
    int tx4, int ty4)
{
#pragma unroll
    for (int kk = 0; kk < 8; ++kk) {
        float4 wv[8];
#pragma unroll
        for (int r = 0; r < 8; ++r)
            wv[r] = *(const float4*)&W[(ty4 + 8 * r) * CC + cb + kk * 4];
#pragma unroll
        for (int j = 0; j < 4; ++j) {
            const float4* hp = (const float4*)&Bs[(kk * 4 + j) * XDP + 8 * tx4];
            float4 h01 = hp[0];            // v0,v0,v1,v1
            float4 h23 = hp[1];            // v2,v2,v3,v3
#pragma unroll
            for (int r = 0; r < 8; ++r) {
                float ws = (j == 0) ? wv[r].x : (j == 1) ? wv[r].y
                         : (j == 2) ? wv[r].z : wv[r].w;
                yacc[r][0] += ws * h01.x;
                yacc[r][1] += ws * h01.z;
                yacc[r][2] += ws * h23.x;
                yacc[r][3] += ws * h23.z;
            }
        }
    }
}

__global__ __launch_bounds__(512, 1)
void gcn_fused_kernel(
    const float* __restrict__ x,      // [8][32][256][64]
    const float* __restrict__ base0,  // [8][64][256][256]
    const float* __restrict__ base1,
    const float* __restrict__ base2,
    const float* __restrict__ W,      // [64][224]
    const float* __restrict__ bias,   // [64]
    float* __restrict__ y)            // [8][64][256][64]
{
    extern __shared__ float smem[];
    float* Xs  = smem;                  // 32*512 = 16384 fl (dup'd)
    float* X1s = Xs  + 16384;           // 16384 fl (dup'd)
    float* As0 = X1s + 16384;           // 8192
    float* As1 = As0 + 8192;            // 8192
    float* As2 = As1 + 8192;            // 8192  -> total 57344 fl = 224 KB

    const int t   = threadIdx.x;
    const int tx4 = t & 63;
    const int ty4 = t >> 6;
    const int bm  = blockIdx.x;
    const int b   = bm >> 6;
    const int m   = bm & 63;

    // Load X dup'd: Xs[f][2n] = Xs[f][2n+1] = x[b][f][n][m]
#pragma unroll
    for (int i = t; i < F_ * NN; i += 512) {
        int f = i >> 8, n = i & 255;
        float v = x[(((size_t)b * F_ + f) * NN + n) * MM + m];
        float2* d = (float2*)&Xs[f * XDP + 2 * n];
        *d = make_float2(v, v);
    }
    __syncthreads();

    float yacc[8][4];
#pragma unroll
    for (int r = 0; r < 8; ++r) {
        float bb = bias[ty4 + 8 * r];
#pragma unroll
        for (int c = 0; c < 4; ++c) yacc[r][c] = bb;
    }

    // slot 0: Y += W[:,0:32] * X
    mix_step(Xs, W, 0, yacc, tx4, ty4);

    const float* bases[3] = { base0, base1, base2 };
#pragma unroll 1
    for (int iB = 0; iB < 3; ++iB) {
        const float* Ag = bases[iB] + (size_t)bm * (NN * NN);

        nconv_step(Ag, Xs, X1s, As0, As1, As2, t, tx4, ty4);
        mix_step(X1s, W, 32 + iB * 64, yacc, tx4, ty4);

        nconv_step(Ag, X1s, X1s, As0, As1, As2, t, tx4, ty4);  // in-place
        mix_step(X1s, W, 64 + iB * 64, yacc, tx4, ty4);
    }

    // Store y[b][o][v][m]
#pragma unroll
    for (int r = 0; r < 8; ++r) {
        int o = ty4 + 8 * r;
#pragma unroll
        for (int j = 0; j < 4; ++j) {
            int v = tx4 * 4 + j;
            y[(((size_t)b * CO + o) * NN + v) * MM + m] = yacc[r][j];
        }
    }
}

extern "C" void kernel_launch(void* const* d_in, const int* in_sizes, int n_in,
                              void* d_out, int out_size)
{
    const float* x     = (const float*)d_in[0];
    const float* base0 = (const float*)d_in[1];
    const float* base1 = (const float*)d_in[2];
    const float* base2 = (const float*)d_in[3];
    const float* W     = (const float*)d_in[4];
    const float* bias  = (const float*)d_in[5];
    float* y = (float*)d_out;

    const int smem_bytes = 57344 * (int)sizeof(float);   // 229376 B = 224 KB
    cudaFuncSetAttribute(gcn_fused_kernel,
                         cudaFuncAttributeMaxDynamicSharedMemorySize, smem_bytes);

    gcn_fused_kernel<<<B_ * MM, 512, smem_bytes>>>(x, base0, base1, base2, W, bias, y);
}

// round 15
// speedup vs baseline: 1.6108x; 1.6108x over previous
#include <cuda_runtime.h>
#include <cstdint>

// Problem constants
#define B_   8
#define F_   32
#define NN   256
#define MM   64
#define CO   64
#define CC   224
#define XDP  512     // dup'd X-tile row pitch in floats (each value stored twice)

typedef unsigned long long u64;

__device__ __forceinline__ float2 unpk2(u64 v) {
    float2 f; asm("mov.b64 {%0, %1}, %2;" : "=f"(f.x), "=f"(f.y) : "l"(v)); return f;
}
__device__ __forceinline__ u64 ffma2(u64 a, u64 b, u64 c) {
    u64 d; asm("fma.rn.f32x2 %0, %1, %2, %3;" : "=l"(d) : "l"(a), "l"(b), "l"(c)); return d;
}

// ---- cp.async ----
__device__ __forceinline__ void cp_async16(void* smem_dst, const void* gmem_src) {
    uint32_t s = (uint32_t)__cvta_generic_to_shared(smem_dst);
    asm volatile("cp.async.cg.shared.global [%0], [%1], 16;\n" :: "r"(s), "l"(gmem_src));
}
__device__ __forceinline__ void cp_commit() { asm volatile("cp.async.commit_group;\n"); }
template <int N>
__device__ __forceinline__ void cp_wait() { asm volatile("cp.async.wait_group %0;\n" :: "n"(N)); }

__device__ __forceinline__ void issue_panel_copy(float* dst, const float* src, int t) {
    const float4* s4 = (const float4*)src;
    float4* d4 = (float4*)dst;
#pragma unroll
    for (int i = 0; i < 4; ++i)          // 2048 float4 / 512 threads
        cp_async16(&d4[t + 512 * i], &s4[t + 512 * i]);
    cp_commit();
}

// X1[f][v] = sum_n X[f][n] * A[n][v].
// X tiles are stored DUPLICATED: Xdup[f][2n] == Xdup[f][2n+1] == X[f][n],
// so the FFMA2 "broadcast" operand is a direct 16B LDS (2 dup-pairs), no packs.
// Thread (ty4 = t>>6, tx4 = t&63): rows {ty4+8r, r<4}, cols {4*tx4 .. 4*tx4+3}.
// A loads: 1 x LDS.128 per k, reused by 4 rows (same as the 596us kernel).
__device__ __forceinline__ void nconv_step(
    const float* __restrict__ Ag,     // global A[b][m]: [256][256] fp32
    const float* Xsrc, float* Xdst,   // dup'd smem tiles [32][XDP] (may alias)
    float* As0, float* As1, float* As2,
    int t, int tx4, int ty4)
{
    u64 acc[4][2];
#pragma unroll
    for (int r = 0; r < 4; ++r) { acc[r][0] = 0ull; acc[r][1] = 0ull; }

    float* bufs[3] = { As0, As1, As2 };
    issue_panel_copy(As0, Ag, t);
    issue_panel_copy(As1, Ag + 8192, t);

#pragma unroll 1
    for (int kp = 0; kp < 8; ++kp) {
        if (kp < 7) cp_wait<1>(); else cp_wait<0>();
        __syncthreads();                       // panel kp visible to all
        if (kp + 2 < 8)
            issue_panel_copy(bufs[(kp + 2) % 3], Ag + (kp + 2) * 8192, t);
        // 3 buffers: buf (kp+2)%3 was last read at iter kp-1, which completed
        // before the barrier above -> no tail barrier needed.

        const float* As = bufs[kp % 3];

#pragma unroll 4
        for (int kq = 0; kq < 16; ++kq) {      // 2 k per iteration
            // dup-pair X loads: 16B broadcast per row = (dup(k0), dup(k1))
            ulonglong2 xp[4];
#pragma unroll
            for (int r = 0; r < 4; ++r)
                xp[r] = *(const ulonglong2*)&Xsrc[(ty4 + 8 * r) * XDP + kp * 64 + kq * 4];
#pragma unroll
            for (int j2 = 0; j2 < 2; ++j2) {
                int k = kq * 2 + j2;
                ulonglong2 a2 = *(const ulonglong2*)&As[k * NN + tx4 * 4];
#pragma unroll
                for (int r = 0; r < 4; ++r) {
                    u64 xd = j2 ? xp[r].y : xp[r].x;
                    acc[r][0] = ffma2(xd, a2.x, acc[r][0]);
                    acc[r][1] = ffma2(xd, a2.y, acc[r][1]);
                }
            }
        }
    }

    __syncthreads();   // all reads of Xsrc done -> in-place overwrite safe
#pragma unroll
    for (int r = 0; r < 4; ++r) {
        int row = ty4 + 8 * r;
        float2 p0 = unpk2(acc[r][0]);
        float2 p1 = unpk2(acc[r][1]);
        float4* d = (float4*)&Xdst[row * XDP + 8 * tx4];
        d[0] = make_float4(p0.x, p0.x, p0.y, p0.y);   // dup'd store
        d[1] = make_float4(p1.x, p1.x, p1.y, p1.y);
    }
    __syncthreads();   // Xdst visible
}

// Y[o][v] += sum_c W[o][cb+c] * h[c][v] over c in [0,32).  Scalar FFMA (12.7%
// of MACs).  h comes from a dup'd tile: two 16B loads give v0,v0,v1,v1 / v2,...
__device__ __forceinline__ void mix_step(
    const float* Bs,                  // dup'd smem tile [32][XDP]
    const float* __restrict__ W,      // [64][224] global (L1-resident)
    int cb,
    float (&yacc)[8][4],
    int tx4, int ty4)
{
#pragma unroll
    for (int kk = 0; kk < 8; ++kk) {
        float4 wv[8];
#pragma unroll
        for (int r = 0; r < 8; ++r)
            wv[r] = *(const float4*)&W[(ty4 + 8 * r) * CC + cb + kk * 4];
#pragma unroll
        for (int j = 0; j < 4; ++j) {
            const float4* hp = (const float4*)&Bs[(kk * 4 + j) * XDP + 8 * tx4];
            float4 h01 = hp[0];            // v0,v0,v1,v1
            float4 h23 = hp[1];            // v2,v2,v3,v3
#pragma unroll
            for (int r = 0; r < 8; ++r) {
                float ws = (j == 0) ? wv[r].x : (j == 1) ? wv[r].y
                         : (j == 2) ? wv[r].z : wv[r].w;
                yacc[r][0] += ws * h01.x;
                yacc[r][1] += ws * h01.z;
                yacc[r][2] += ws * h23.x;
                yacc[r][3] += ws * h23.z;
            }
        }
    }
}

__global__ __launch_bounds__(512, 1)
void gcn_fused_kernel(
    const float* __restrict__ x,      // [8][32][256][64]
    const float* __restrict__ base0,  // [8][64][256][256]
    const float* __restrict__ base1,
    const float* __restrict__ base2,
    const float* __restrict__ W,      // [64][224]
    const float* __restrict__ bias,   // [64]
    float* __restrict__ y)            // [8][64][256][64]
{
    extern __shared__ float smem[];
    float* Xs  = smem;                  // 32*512 = 16384 fl (dup'd)
    float* X1s = Xs  + 16384;           // 16384 fl (dup'd)
    float* As0 = X1s + 16384;           // 8192
    float* As1 = As0 + 8192;            // 8192
    float* As2 = As1 + 8192;            // 8192  -> total 57344 fl = 224 KB

    const int t   = threadIdx.x;
    const int tx4 = t & 63;
    const int ty4 = t >> 6;
    const int bm  = blockIdx.x;
    const int b   = bm >> 6;
    const int m   = bm & 63;

    // Load X dup'd: Xs[f][2n] = Xs[f][2n+1] = x[b][f][n][m]
#pragma unroll
    for (int i = t; i < F_ * NN; i += 512) {
        int f = i >> 8, n = i & 255;
        float v = x[(((size_t)b * F_ + f) * NN + n) * MM + m];
        float2* d = (float2*)&Xs[f * XDP + 2 * n];
        *d = make_float2(v, v);
    }
    __syncthreads();

    float yacc[8][4];
#pragma unroll
    for (int r = 0; r < 8; ++r) {
        float bb = bias[ty4 + 8 * r];
#pragma unroll
        for (int c = 0; c < 4; ++c) yacc[r][c] = bb;
    }

    // slot 0: Y += W[:,0:32] * X
    mix_step(Xs, W, 0, yacc, tx4, ty4);

    const float* bases[3] = { base0, base1, base2 };
#pragma unroll 1
    for (int iB = 0; iB < 3; ++iB) {
        const float* Ag = bases[iB] + (size_t)bm * (NN * NN);

        nconv_step(Ag, Xs, X1s, As0, As1, As2, t, tx4, ty4);
        mix_step(X1s, W, 32 + iB * 64, yacc, tx4, ty4);

        nconv_step(Ag, X1s, X1s, As0, As1, As2, t, tx4, ty4);  // in-place
        mix_step(X1s, W, 64 + iB * 64, yacc, tx4, ty4);
    }

    // Store y[b][o][v][m]
#pragma unroll
    for (int r = 0; r < 8; ++r) {
        int o = ty4 + 8 * r;
#pragma unroll
        for (int j = 0; j < 4; ++j) {
            int v = tx4 * 4 + j;
            y[(((size_t)b * CO + o) * NN + v) * MM + m] = yacc[r][j];
        }
    }
}

extern "C" void kernel_launch(void* const* d_in, const int* in_sizes, int n_in,
                              void* d_out, int out_size)
{
    const float* x     = (const float*)d_in[0];
    const float* base0 = (const float*)d_in[1];
    const float* base1 = (const float*)d_in[2];
    const float* base2 = (const float*)d_in[3];
    const float* W     = (const float*)d_in[4];
    const float* bias  = (const float*)d_in[5];
    float* y = (float*)d_out;

    const int smem_bytes = 57344 * (int)sizeof(float);   // 229376 B = 224 KB
    cudaFuncSetAttribute(gcn_fused_kernel,
                         cudaFuncAttributeMaxDynamicSharedMemorySize, smem_bytes);

    gcn_fused_kernel<<<B_ * MM, 512, smem_bytes>>>(x, base0, base1, base2, W, bias, y);
}